// round 8
// baseline (speedup 1.0000x reference)
#include <cuda_runtime.h>
#include <math.h>

// ---------------------------------------------------------------------------
// Problem constants
// ---------------------------------------------------------------------------
#define NB    64
#define CIN   32
#define COUT  32
#define SUBD  12
#define UPD   26
#define D0    24
#define D1    22
#define D2    20
#define TSD   74
#define PRED_OFF 28311552 // 512*32*12*12*12

// ---------------------------------------------------------------------------
// Packed fp32x2 helpers (kept ONLY for upsample where measured speed-neutral)
// ---------------------------------------------------------------------------
__device__ __forceinline__ void ffma2(unsigned long long& d,
                                      unsigned long long a,
                                      unsigned long long b) {
    asm("fma.rn.f32x2 %0, %1, %2, %0;" : "+l"(d) : "l"(a), "l"(b));
}
__device__ __forceinline__ unsigned long long pk2(float lo, float hi) {
    unsigned long long r;
    asm("mov.b64 %0, {%1, %2};" : "=l"(r) : "f"(lo), "f"(hi));
    return r;
}
__device__ __forceinline__ void upk2(unsigned long long v, float& lo, float& hi) {
    asm("mov.b64 {%0, %1}, %2;" : "=f"(lo), "=f"(hi) : "l"(v));
}

// ---------------------------------------------------------------------------
// Device scratch (static allocation — no cudaMalloc allowed)
// ---------------------------------------------------------------------------
__device__ float g_x0[NB * 33 * UPD * UPD * UPD];
__device__ float g_x1[NB * 32 * D0 * D0 * D0];
__device__ float g_x2[NB * 32 * D1 * D1 * D1];
__device__ float g_h0[NB * 16 * 10 * 10 * 10];

// ---------------------------------------------------------------------------
// Prediction branch, stage 0: conv3d 32->16 (12^3 -> 10^3) + BN + ReLU
// ---------------------------------------------------------------------------
__global__ void pred_p0_kernel(const float* __restrict__ prev,
                               const float* __restrict__ w,    // [16][32][27]
                               const float* __restrict__ gam,
                               const float* __restrict__ bet) {
    const int n = blockIdx.x;
    const int tid = threadIdx.x;
    __shared__ float ch[1728];
    __shared__ float wsm[432];

    float acc[2][16];
#pragma unroll
    for (int i = 0; i < 2; i++)
#pragma unroll
        for (int c = 0; c < 16; c++) acc[i][c] = 0.f;

    const int p0 = tid, p1 = tid + 512;
    const int z0 = p0 / 100, y0 = (p0 / 10) % 10, x0 = p0 % 10;
    const int z1 = p1 / 100, y1 = (p1 / 10) % 10, x1 = p1 % 10;
    const bool v0 = (p0 < 1000), v1 = (p1 < 1000);

    for (int ci = 0; ci < 32; ci++) {
        for (int t = tid; t < 1728; t += 512)
            ch[t] = prev[(n * 32 + ci) * 1728 + t];
        if (tid < 432) {
            int co = tid / 27, tap = tid % 27;
            wsm[tid] = w[(co * 32 + ci) * 27 + tap];
        }
        __syncthreads();
#pragma unroll
        for (int kz = 0; kz < 3; kz++)
#pragma unroll
            for (int ky = 0; ky < 3; ky++)
#pragma unroll
                for (int kx = 0; kx < 3; kx++) {
                    const int tap = kz * 9 + ky * 3 + kx;
                    float iv0 = v0 ? ch[(z0 + kz) * 144 + (y0 + ky) * 12 + (x0 + kx)] : 0.f;
                    float iv1 = v1 ? ch[(z1 + kz) * 144 + (y1 + ky) * 12 + (x1 + kx)] : 0.f;
#pragma unroll
                    for (int co = 0; co < 16; co++) {
                        float wv = wsm[co * 27 + tap];
                        acc[0][co] += wv * iv0;
                        acc[1][co] += wv * iv1;
                    }
                }
        __syncthreads();
    }
    const float rs = rsqrtf(1.f + 1e-5f);
#pragma unroll
    for (int co = 0; co < 16; co++) {
        float s = gam[co] * rs, bb = bet[co];
        if (v0) g_h0[(n * 16 + co) * 1000 + p0] = fmaxf(acc[0][co] * s + bb, 0.f);
        if (v1) g_h0[(n * 16 + co) * 1000 + p1] = fmaxf(acc[1][co] * s + bb, 0.f);
    }
}

// ---------------------------------------------------------------------------
// Prediction branch, stage 1
// ---------------------------------------------------------------------------
__global__ void pred_p1_kernel(const float* __restrict__ w1,   // [8][16][27]
                               const float* __restrict__ g1,
                               const float* __restrict__ b1,
                               const float* __restrict__ wl,   // [3][8]
                               const float* __restrict__ bl,
                               float* __restrict__ out_pred) {
    const int n = blockIdx.x;
    const int tid = threadIdx.x;
    __shared__ float hp[16 * 125];
    __shared__ float c2[8 * 27];
    __shared__ float pl[8];

    for (int t = tid; t < 2000; t += 256) {
        int co = t / 125, p = t % 125;
        int z = p / 25, y = (p / 5) % 5, x = p % 5;
        const float* hb = g_h0 + (n * 16 + co) * 1000;
        float m = -INFINITY;
#pragma unroll
        for (int dz = 0; dz < 2; dz++)
#pragma unroll
            for (int dy = 0; dy < 2; dy++)
#pragma unroll
                for (int dx = 0; dx < 2; dx++)
                    m = fmaxf(m, hb[(2 * z + dz) * 100 + (2 * y + dy) * 10 + (2 * x + dx)]);
        hp[t] = m;
    }
    __syncthreads();
    if (tid < 216) {
        int co = tid / 27, p = tid % 27;
        int z = p / 9, y = (p / 3) % 3, x = p % 3;
        float acc = 0.f;
        for (int ci = 0; ci < 16; ci++)
#pragma unroll
            for (int kz = 0; kz < 3; kz++)
#pragma unroll
                for (int ky = 0; ky < 3; ky++)
#pragma unroll
                    for (int kx = 0; kx < 3; kx++)
                        acc += hp[ci * 125 + (z + kz) * 25 + (y + ky) * 5 + (x + kx)] *
                               __ldg(&w1[(co * 16 + ci) * 27 + kz * 9 + ky * 3 + kx]);
        const float rs = rsqrtf(1.f + 1e-5f);
        c2[tid] = fmaxf(acc * g1[co] * rs + b1[co], 0.f);
    }
    __syncthreads();
    if (tid < 8) {
        float m = -INFINITY;
#pragma unroll
        for (int dz = 0; dz < 2; dz++)
#pragma unroll
            for (int dy = 0; dy < 2; dy++)
#pragma unroll
                for (int dx = 0; dx < 2; dx++)
                    m = fmaxf(m, c2[tid * 27 + dz * 9 + dy * 3 + dx]);
        pl[tid] = m;
    }
    __syncthreads();
    if (tid < 3) {
        float acc = bl[tid];
#pragma unroll
        for (int j = 0; j < 8; j++) acc += pl[j] * wl[tid * 8 + j];
        out_pred[n * 3 + tid] = acc;
    }
}

// ---------------------------------------------------------------------------
// tsdf slice -> channel 32 of x0
// ---------------------------------------------------------------------------
__global__ void tsdf_slice_kernel(const float* __restrict__ tsdf) {
    int idx = blockIdx.x * blockDim.x + threadIdx.x;
    const int TOT = NB * UPD * UPD * UPD;
    if (idx >= TOT) return;
    int n = idx / (UPD * UPD * UPD);
    int p = idx % (UPD * UPD * UPD);
    int z = p / (UPD * UPD), y = (p / UPD) % UPD, x = p % UPD;
    int a = n >> 4, b = (n >> 2) & 3, c = n & 3;
    float v = tsdf[(a * 16 + z) * TSD * TSD + (b * 16 + y) * TSD + (c * 16 + x)];
    g_x0[(n * 33 + 32) * (UPD * UPD * UPD) + p] = v;
}

// ---------------------------------------------------------------------------
// ConvTranspose upsample (FFMA2 over cout pairs — measured speed-neutral, keep)
// ---------------------------------------------------------------------------
__global__ void upsample_kernel(const float* __restrict__ prev,
                                const float* __restrict__ wup) { // [co][ci][4][4][4]
    const int n = blockIdx.x;
    const int z = blockIdx.y;
    const int tid = threadIdx.x;
    __shared__ float ism[2 * 32 * 144];
    __shared__ __align__(16) float wsm[1024];

    const int izA = z >> 1;
    const int izB = izA - 1;

    for (int t = tid; t < 2 * 32 * 144; t += blockDim.x) {
        int kzi = t / (32 * 144);
        int rem = t % (32 * 144);
        int ci = rem / 144, pi = rem % 144;
        int iz = kzi ? izB : izA;
        float v = 0.f;
        if (iz >= 0 && iz < 12) v = prev[((n * 32 + ci) * 12 + iz) * 144 + pi];
        ism[t] = v;
    }

    const int p = tid;
    const bool pv = (p < 676);
    const int y = p / 26, x = p % 26;
    const int iyA = y >> 1, ixA = x >> 1;
    const int kyb = y & 1, kxb = x & 1;

    unsigned long long acc[16];
#pragma unroll
    for (int i = 0; i < 16; i++) acc[i] = 0ull;

    for (int ci = 0; ci < 32; ci++) {
        for (int t = tid; t < 1024; t += blockDim.x) {
            int kk = t >> 5;
            int co = t & 31;
            int kzi = kk >> 4, ky = (kk >> 2) & 3, kx = kk & 3;
            int kz = (z & 1) + 2 * kzi;
            wsm[t] = wup[((co * 32 + ci) * 4 + kz) * 16 + ky * 4 + kx];
        }
        __syncthreads();
        if (pv) {
            const float* ib = ism + ci * 144;
#pragma unroll
            for (int kzi = 0; kzi < 2; kzi++)
#pragma unroll
                for (int kyi = 0; kyi < 2; kyi++)
#pragma unroll
                    for (int kxi = 0; kxi < 2; kxi++) {
                        int iy = iyA - kyi, ix = ixA - kxi;
                        if (iy < 0 || iy >= 12 || ix < 0 || ix >= 12) continue;
                        float iv = ib[kzi * 4608 + iy * 12 + ix];
                        unsigned long long ivp = pk2(iv, iv);
                        int kk = (kzi * 4 + (kyb + 2 * kyi)) * 4 + (kxb + 2 * kxi);
                        const ulonglong2* w2p = (const ulonglong2*)wsm + kk * 8;
#pragma unroll
                        for (int q = 0; q < 8; q++) {
                            ulonglong2 ww = w2p[q];
                            ffma2(acc[2 * q + 0], ivp, ww.x);
                            ffma2(acc[2 * q + 1], ivp, ww.y);
                        }
                    }
        }
        __syncthreads();
    }
    if (pv) {
#pragma unroll
        for (int k = 0; k < 16; k++) {
            float lo, hi;
            upk2(acc[k], lo, hi);
            g_x0[(n * 33 + 2 * k + 0) * (UPD * UPD * UPD) + z * 676 + p] = lo;
            g_x0[(n * 33 + 2 * k + 1) * (UPD * UPD * UPD) + z * 676 + p] = hi;
        }
    }
}

// ---------------------------------------------------------------------------
// Conv3d k=3 valid + BN + ReLU. Scalar FFMA, double-buffered staging.
// NEW: padded smem row stride (RS % 4 == 0) + register row caching:
//      each (kz,ky) row of 10 floats loaded once as float4/float4/float2,
//      all 3 kx taps consume from registers. LDS per ci: ~190 -> 54.
// grid = (zo, ytile, n). 192 threads = 24 spatial groups x 8 cout-groups.
// SPLIT: write c2 result directly into subtree children of d_out.
// ---------------------------------------------------------------------------
template <int CINL, int WOUT, bool SPLIT>
__global__ void conv3_bnrelu_kernel(const float* __restrict__ in,
                                    const float* __restrict__ w,   // [32][CINL][27]
                                    const float* __restrict__ gam,
                                    const float* __restrict__ bet,
                                    float* __restrict__ out) {
    constexpr int WIN = WOUT + 2;
    constexpr int RS  = (WIN + 3) & ~3;        // padded row stride (16B aligned)
    constexpr int ISM = 3 * 10 * RS + 8;       // +8 pad for tail float2 overread
    const int zo = blockIdx.x;
    const int y0 = blockIdx.y * 8;
    const int n = blockIdx.z;

    __shared__ __align__(16) float ism[2][ISM];
    __shared__ __align__(16) float wsm[2][27 * 32];

    const int tid = threadIdx.x;
    const int cog = tid & 7;
    const int sp = tid >> 3;
    const int xg = sp % 3;
    const int yr = sp / 3;
    const int xb = xg * 8;
    const int y = y0 + yr;

    float a0[8], a1[8], a2[8], a3[8];
#pragma unroll
    for (int j = 0; j < 8; j++) { a0[j] = a1[j] = a2[j] = a3[j] = 0.f; }

    const float* inb = in + (size_t)n * CINL * WIN * WIN * WIN;

    // stage channel ci into buffer buf (padded row stride RS)
    auto stage = [&](int ci, int buf) {
        const float* inc = inb + (size_t)ci * WIN * WIN * WIN;
        for (int t = tid; t < 3 * 10 * WIN; t += 192) {
            int iz = t / (10 * WIN);
            int rem = t - iz * 10 * WIN;
            int iy = rem / WIN;
            int ix = rem - iy * WIN;
            int gy = y0 + iy;
            ism[buf][(iz * 10 + iy) * RS + ix] =
                (gy < WIN) ? inc[(zo + iz) * WIN * WIN + gy * WIN + ix] : 0.f;
        }
        for (int t = tid; t < 864; t += 192) {
            int tap = t >> 5, co = t & 31;
            wsm[buf][t] = w[(co * CINL + ci) * 27 + tap];
        }
    };

    stage(0, 0);
    __syncthreads();

    for (int ci = 0; ci < CINL; ci++) {
        const int buf = ci & 1;
        if (ci + 1 < CINL) stage(ci + 1, buf ^ 1);   // prefetch overlaps compute
#pragma unroll
        for (int kz = 0; kz < 3; kz++)
#pragma unroll
            for (int ky = 0; ky < 3; ky++) {
                const float* row = &ism[buf][(kz * 10 + yr + ky) * RS + xb];
                // load the 10-float row once (aligned vector LDS)
                float4 v0 = *(const float4*)(row);
                float4 v1 = *(const float4*)(row + 4);
                float2 v2 = *(const float2*)(row + 8);
                float r[10] = {v0.x, v0.y, v0.z, v0.w,
                               v1.x, v1.y, v1.z, v1.w,
                               v2.x, v2.y};
#pragma unroll
                for (int kx = 0; kx < 3; kx++) {
                    float4 w4 = ((const float4*)wsm[buf])[(kz * 9 + ky * 3 + kx) * 8 + cog];
#pragma unroll
                    for (int j = 0; j < 8; j++) {
                        float iv = r[j + kx];
                        a0[j] += w4.x * iv;
                        a1[j] += w4.y * iv;
                        a2[j] += w4.z * iv;
                        a3[j] += w4.w * iv;
                    }
                }
            }
        __syncthreads();
    }

    if (y < WOUT) {
        const float rs = rsqrtf(1.f + 1e-5f);
        float* accs[4] = {a0, a1, a2, a3};
#pragma unroll
        for (int c = 0; c < 4; c++) {
            int co = cog * 4 + c;
            float s = gam[co] * rs, bb = bet[co];
#pragma unroll
            for (int j = 0; j < 8; j++) {
                int xx = xb + j;
                if (xx >= WOUT) continue;
                float val = fmaxf(accs[c][j] * s + bb, 0.f);
                if (!SPLIT) {
                    out[(((size_t)(n * 32 + co) * WOUT + zo) * WOUT + y) * WOUT + xx] = val;
                } else {
#pragma unroll
                    for (int cz = 0; cz < 2; cz++) {
                        int dz = zo - cz * 8;
                        if (dz < 0 || dz >= 12) continue;
#pragma unroll
                        for (int cy = 0; cy < 2; cy++) {
                            int dy = y - cy * 8;
                            if (dy < 0 || dy >= 12) continue;
#pragma unroll
                            for (int cx = 0; cx < 2; cx++) {
                                int dx = xx - cx * 8;
                                if (dx < 0 || dx >= 12) continue;
                                int b = n * 8 + (cz << 2) + (cy << 1) + cx;
                                out[((size_t)(b * 32 + co) * 1728) + dz * 144 + dy * 12 + dx] = val;
                            }
                        }
                    }
                }
            }
        }
    }
}

// ---------------------------------------------------------------------------
// Launch
// ---------------------------------------------------------------------------
extern "C" void kernel_launch(void* const* d_in, const int* in_sizes, int n_in,
                              void* d_out, int out_size) {
    const float* prev  = (const float*)d_in[0];
    const float* tsdf  = (const float*)d_in[1];
    const float* w_up  = (const float*)d_in[2];
    const float* w_c0  = (const float*)d_in[3];
    const float* g_c0  = (const float*)d_in[4];
    const float* b_c0  = (const float*)d_in[5];
    const float* w_c1  = (const float*)d_in[6];
    const float* g_c1  = (const float*)d_in[7];
    const float* b_c1  = (const float*)d_in[8];
    const float* w_c2  = (const float*)d_in[9];
    const float* g_c2  = (const float*)d_in[10];
    const float* b_c2  = (const float*)d_in[11];
    const float* w_p0  = (const float*)d_in[12];
    const float* g_p0  = (const float*)d_in[13];
    const float* b_p0  = (const float*)d_in[14];
    const float* w_p1  = (const float*)d_in[15];
    const float* g_p1  = (const float*)d_in[16];
    const float* b_p1  = (const float*)d_in[17];
    const float* w_lin = (const float*)d_in[18];
    const float* b_lin = (const float*)d_in[19];
    float* out = (float*)d_out;

    float* dx0; cudaGetSymbolAddress((void**)&dx0, g_x0);
    float* dx1; cudaGetSymbolAddress((void**)&dx1, g_x1);
    float* dx2; cudaGetSymbolAddress((void**)&dx2, g_x2);

    // build x0 = concat(upsample(prev), tsdf slice)
    {
        int tot = NB * UPD * UPD * UPD;
        tsdf_slice_kernel<<<(tot + 255) / 256, 256>>>(tsdf);
    }
    upsample_kernel<<<dim3(NB, UPD), 704>>>(prev, w_up);

    // conv chain (c2 fused with split_tree scatter into d_out)
    conv3_bnrelu_kernel<33, 24, false><<<dim3(24, 3, NB), 192>>>(dx0, w_c0, g_c0, b_c0, dx1);
    conv3_bnrelu_kernel<32, 22, false><<<dim3(22, 3, NB), 192>>>(dx1, w_c1, g_c1, b_c1, dx2);
    conv3_bnrelu_kernel<32, 20, true ><<<dim3(20, 3, NB), 192>>>(dx2, w_c2, g_c2, b_c2, out);

    // prediction branch (independent — last)
    pred_p0_kernel<<<64, 512>>>(prev, w_p0, g_p0, b_p0);
    pred_p1_kernel<<<64, 256>>>(w_p1, g_p1, b_p1, w_lin, b_lin, out + PRED_OFF);
}

// round 9
// speedup vs baseline: 1.6436x; 1.6436x over previous
#include <cuda_runtime.h>
#include <math.h>

// ---------------------------------------------------------------------------
// Problem constants
// ---------------------------------------------------------------------------
#define NB    64
#define CIN   32
#define COUT  32
#define SUBD  12
#define UPD   26
#define D0    24
#define D1    22
#define D2    20
#define TSD   74
#define PRED_OFF 28311552 // 512*32*12*12*12

// ---------------------------------------------------------------------------
// Packed fp32x2 helpers (kept ONLY for upsample where measured speed-neutral)
// ---------------------------------------------------------------------------
__device__ __forceinline__ void ffma2(unsigned long long& d,
                                      unsigned long long a,
                                      unsigned long long b) {
    asm("fma.rn.f32x2 %0, %1, %2, %0;" : "+l"(d) : "l"(a), "l"(b));
}
__device__ __forceinline__ unsigned long long pk2(float lo, float hi) {
    unsigned long long r;
    asm("mov.b64 %0, {%1, %2};" : "=l"(r) : "f"(lo), "f"(hi));
    return r;
}
__device__ __forceinline__ void upk2(unsigned long long v, float& lo, float& hi) {
    asm("mov.b64 {%0, %1}, %2;" : "=f"(lo), "=f"(hi) : "l"(v));
}

// ---------------------------------------------------------------------------
// Device scratch (static allocation — no cudaMalloc allowed)
// ---------------------------------------------------------------------------
__device__ float g_x0[NB * 33 * UPD * UPD * UPD];
__device__ float g_x1[NB * 32 * D0 * D0 * D0];
__device__ float g_x2[NB * 32 * D1 * D1 * D1];
__device__ float g_h0[NB * 16 * 10 * 10 * 10];

// ---------------------------------------------------------------------------
// Prediction branch, stage 0: conv3d 32->16 (12^3 -> 10^3) + BN + ReLU
// ---------------------------------------------------------------------------
__global__ void pred_p0_kernel(const float* __restrict__ prev,
                               const float* __restrict__ w,    // [16][32][27]
                               const float* __restrict__ gam,
                               const float* __restrict__ bet) {
    const int n = blockIdx.x;
    const int tid = threadIdx.x;
    __shared__ float ch[1728];
    __shared__ float wsm[432];

    float acc[2][16];
#pragma unroll
    for (int i = 0; i < 2; i++)
#pragma unroll
        for (int c = 0; c < 16; c++) acc[i][c] = 0.f;

    const int p0 = tid, p1 = tid + 512;
    const int z0 = p0 / 100, y0 = (p0 / 10) % 10, x0 = p0 % 10;
    const int z1 = p1 / 100, y1 = (p1 / 10) % 10, x1 = p1 % 10;
    const bool v0 = (p0 < 1000), v1 = (p1 < 1000);

    for (int ci = 0; ci < 32; ci++) {
        for (int t = tid; t < 1728; t += 512)
            ch[t] = prev[(n * 32 + ci) * 1728 + t];
        if (tid < 432) {
            int co = tid / 27, tap = tid % 27;
            wsm[tid] = w[(co * 32 + ci) * 27 + tap];
        }
        __syncthreads();
#pragma unroll
        for (int kz = 0; kz < 3; kz++)
#pragma unroll
            for (int ky = 0; ky < 3; ky++)
#pragma unroll
                for (int kx = 0; kx < 3; kx++) {
                    const int tap = kz * 9 + ky * 3 + kx;
                    float iv0 = v0 ? ch[(z0 + kz) * 144 + (y0 + ky) * 12 + (x0 + kx)] : 0.f;
                    float iv1 = v1 ? ch[(z1 + kz) * 144 + (y1 + ky) * 12 + (x1 + kx)] : 0.f;
#pragma unroll
                    for (int co = 0; co < 16; co++) {
                        float wv = wsm[co * 27 + tap];
                        acc[0][co] += wv * iv0;
                        acc[1][co] += wv * iv1;
                    }
                }
        __syncthreads();
    }
    const float rs = rsqrtf(1.f + 1e-5f);
#pragma unroll
    for (int co = 0; co < 16; co++) {
        float s = gam[co] * rs, bb = bet[co];
        if (v0) g_h0[(n * 16 + co) * 1000 + p0] = fmaxf(acc[0][co] * s + bb, 0.f);
        if (v1) g_h0[(n * 16 + co) * 1000 + p1] = fmaxf(acc[1][co] * s + bb, 0.f);
    }
}

// ---------------------------------------------------------------------------
// Prediction branch, stage 1
// ---------------------------------------------------------------------------
__global__ void pred_p1_kernel(const float* __restrict__ w1,   // [8][16][27]
                               const float* __restrict__ g1,
                               const float* __restrict__ b1,
                               const float* __restrict__ wl,   // [3][8]
                               const float* __restrict__ bl,
                               float* __restrict__ out_pred) {
    const int n = blockIdx.x;
    const int tid = threadIdx.x;
    __shared__ float hp[16 * 125];
    __shared__ float c2[8 * 27];
    __shared__ float pl[8];

    for (int t = tid; t < 2000; t += 256) {
        int co = t / 125, p = t % 125;
        int z = p / 25, y = (p / 5) % 5, x = p % 5;
        const float* hb = g_h0 + (n * 16 + co) * 1000;
        float m = -INFINITY;
#pragma unroll
        for (int dz = 0; dz < 2; dz++)
#pragma unroll
            for (int dy = 0; dy < 2; dy++)
#pragma unroll
                for (int dx = 0; dx < 2; dx++)
                    m = fmaxf(m, hb[(2 * z + dz) * 100 + (2 * y + dy) * 10 + (2 * x + dx)]);
        hp[t] = m;
    }
    __syncthreads();
    if (tid < 216) {
        int co = tid / 27, p = tid % 27;
        int z = p / 9, y = (p / 3) % 3, x = p % 3;
        float acc = 0.f;
        for (int ci = 0; ci < 16; ci++)
#pragma unroll
            for (int kz = 0; kz < 3; kz++)
#pragma unroll
                for (int ky = 0; ky < 3; ky++)
#pragma unroll
                    for (int kx = 0; kx < 3; kx++)
                        acc += hp[ci * 125 + (z + kz) * 25 + (y + ky) * 5 + (x + kx)] *
                               __ldg(&w1[(co * 16 + ci) * 27 + kz * 9 + ky * 3 + kx]);
        const float rs = rsqrtf(1.f + 1e-5f);
        c2[tid] = fmaxf(acc * g1[co] * rs + b1[co], 0.f);
    }
    __syncthreads();
    if (tid < 8) {
        float m = -INFINITY;
#pragma unroll
        for (int dz = 0; dz < 2; dz++)
#pragma unroll
            for (int dy = 0; dy < 2; dy++)
#pragma unroll
                for (int dx = 0; dx < 2; dx++)
                    m = fmaxf(m, c2[tid * 27 + dz * 9 + dy * 3 + dx]);
        pl[tid] = m;
    }
    __syncthreads();
    if (tid < 3) {
        float acc = bl[tid];
#pragma unroll
        for (int j = 0; j < 8; j++) acc += pl[j] * wl[tid * 8 + j];
        out_pred[n * 3 + tid] = acc;
    }
}

// ---------------------------------------------------------------------------
// tsdf slice -> channel 32 of x0
// ---------------------------------------------------------------------------
__global__ void tsdf_slice_kernel(const float* __restrict__ tsdf) {
    int idx = blockIdx.x * blockDim.x + threadIdx.x;
    const int TOT = NB * UPD * UPD * UPD;
    if (idx >= TOT) return;
    int n = idx / (UPD * UPD * UPD);
    int p = idx % (UPD * UPD * UPD);
    int z = p / (UPD * UPD), y = (p / UPD) % UPD, x = p % UPD;
    int a = n >> 4, b = (n >> 2) & 3, c = n & 3;
    float v = tsdf[(a * 16 + z) * TSD * TSD + (b * 16 + y) * TSD + (c * 16 + x)];
    g_x0[(n * 33 + 32) * (UPD * UPD * UPD) + p] = v;
}

// ---------------------------------------------------------------------------
// ConvTranspose upsample (FFMA2 over cout pairs — measured speed-neutral, keep)
// ---------------------------------------------------------------------------
__global__ void upsample_kernel(const float* __restrict__ prev,
                                const float* __restrict__ wup) { // [co][ci][4][4][4]
    const int n = blockIdx.x;
    const int z = blockIdx.y;
    const int tid = threadIdx.x;
    __shared__ float ism[2 * 32 * 144];
    __shared__ __align__(16) float wsm[1024];

    const int izA = z >> 1;
    const int izB = izA - 1;

    for (int t = tid; t < 2 * 32 * 144; t += blockDim.x) {
        int kzi = t / (32 * 144);
        int rem = t % (32 * 144);
        int ci = rem / 144, pi = rem % 144;
        int iz = kzi ? izB : izA;
        float v = 0.f;
        if (iz >= 0 && iz < 12) v = prev[((n * 32 + ci) * 12 + iz) * 144 + pi];
        ism[t] = v;
    }

    const int p = tid;
    const bool pv = (p < 676);
    const int y = p / 26, x = p % 26;
    const int iyA = y >> 1, ixA = x >> 1;
    const int kyb = y & 1, kxb = x & 1;

    unsigned long long acc[16];
#pragma unroll
    for (int i = 0; i < 16; i++) acc[i] = 0ull;

    for (int ci = 0; ci < 32; ci++) {
        for (int t = tid; t < 1024; t += blockDim.x) {
            int kk = t >> 5;
            int co = t & 31;
            int kzi = kk >> 4, ky = (kk >> 2) & 3, kx = kk & 3;
            int kz = (z & 1) + 2 * kzi;
            wsm[t] = wup[((co * 32 + ci) * 4 + kz) * 16 + ky * 4 + kx];
        }
        __syncthreads();
        if (pv) {
            const float* ib = ism + ci * 144;
#pragma unroll
            for (int kzi = 0; kzi < 2; kzi++)
#pragma unroll
                for (int kyi = 0; kyi < 2; kyi++)
#pragma unroll
                    for (int kxi = 0; kxi < 2; kxi++) {
                        int iy = iyA - kyi, ix = ixA - kxi;
                        if (iy < 0 || iy >= 12 || ix < 0 || ix >= 12) continue;
                        float iv = ib[kzi * 4608 + iy * 12 + ix];
                        unsigned long long ivp = pk2(iv, iv);
                        int kk = (kzi * 4 + (kyb + 2 * kyi)) * 4 + (kxb + 2 * kxi);
                        const ulonglong2* w2p = (const ulonglong2*)wsm + kk * 8;
#pragma unroll
                        for (int q = 0; q < 8; q++) {
                            ulonglong2 ww = w2p[q];
                            ffma2(acc[2 * q + 0], ivp, ww.x);
                            ffma2(acc[2 * q + 1], ivp, ww.y);
                        }
                    }
        }
        __syncthreads();
    }
    if (pv) {
#pragma unroll
        for (int k = 0; k < 16; k++) {
            float lo, hi;
            upk2(acc[k], lo, hi);
            g_x0[(n * 33 + 2 * k + 0) * (UPD * UPD * UPD) + z * 676 + p] = lo;
            g_x0[(n * 33 + 2 * k + 1) * (UPD * UPD * UPD) + z * 676 + p] = hi;
        }
    }
}

// ---------------------------------------------------------------------------
// Conv3d k=3 valid + BN + ReLU. Round-6 proven scalar inner loop +
// double-buffered staging. NEW (round 9): staging addresses hoisted out of
// the ci loop into per-thread registers (no div/mod in the hot loop).
// grid = (zo, ytile, n). 192 threads = 24 spatial groups x 8 cout-groups.
// SPLIT: write c2 result directly into subtree children of d_out.
// ---------------------------------------------------------------------------
template <int CINL, int WOUT, bool SPLIT>
__global__ void conv3_bnrelu_kernel(const float* __restrict__ in,
                                    const float* __restrict__ w,   // [32][CINL][27]
                                    const float* __restrict__ gam,
                                    const float* __restrict__ bet,
                                    float* __restrict__ out) {
    constexpr int WIN = WOUT + 2;
    constexpr int ISM  = 3 * 10 * WIN;
    constexpr int NSTG = (ISM + 191) / 192;    // input staging slots per thread
    constexpr int NW   = (864 + 191) / 192;    // weight staging slots per thread (5)
    constexpr int CH3  = WIN * WIN * WIN;

    const int zo = blockIdx.x;
    const int y0 = blockIdx.y * 8;
    const int n = blockIdx.z;

    __shared__ float ism[2][ISM];
    __shared__ __align__(16) float wsm[2][27 * 32];

    const int tid = threadIdx.x;
    const int cog = tid & 7;
    const int sp = tid >> 3;
    const int xg = sp % 3;
    const int yr = sp / 3;
    const int xb = xg * 8;
    const int y = y0 + yr;

    // ---- hoisted staging addresses (invariant across ci) ----
    int   s_off[NSTG];       // smem offset (== linear t)
    int   g_off[NSTG];       // gmem offset within channel, or -1 for zero-fill/skip
#pragma unroll
    for (int k = 0; k < NSTG; k++) {
        int t = tid + k * 192;
        if (t < ISM) {
            int iz = t / (10 * WIN);
            int rem = t - iz * 10 * WIN;
            int iy = rem / WIN;
            int ix = rem - iy * WIN;
            int gy = y0 + iy;
            s_off[k] = t;
            g_off[k] = (gy < WIN) ? ((zo + iz) * WIN * WIN + gy * WIN + ix) : -1;
        } else {
            s_off[k] = -1;
            g_off[k] = -1;
        }
    }
    int wg_off[NW];          // gmem weight offset for ci=0, or -1
    int ws_off[NW];
#pragma unroll
    for (int k = 0; k < NW; k++) {
        int t = tid + k * 192;
        if (t < 864) {
            int tap = t >> 5, co = t & 31;
            ws_off[k] = t;
            wg_off[k] = (co * CINL) * 27 + tap;   // + ci*27 per channel
        } else {
            ws_off[k] = -1;
            wg_off[k] = -1;
        }
    }

    float a0[8], a1[8], a2[8], a3[8];
#pragma unroll
    for (int j = 0; j < 8; j++) { a0[j] = a1[j] = a2[j] = a3[j] = 0.f; }

    const float* inb = in + (size_t)n * CINL * CH3;

    // stage channel ci into buffer buf (pure LDG+STS, no address math)
    auto stage = [&](int ci, int buf) {
        const float* inc = inb + (size_t)ci * CH3;
#pragma unroll
        for (int k = 0; k < NSTG; k++) {
            if (s_off[k] >= 0)
                ism[buf][s_off[k]] = (g_off[k] >= 0) ? inc[g_off[k]] : 0.f;
        }
        const int wci = ci * 27;
#pragma unroll
        for (int k = 0; k < NW; k++) {
            if (ws_off[k] >= 0)
                wsm[buf][ws_off[k]] = w[wg_off[k] + wci];
        }
    };

    stage(0, 0);
    __syncthreads();

    for (int ci = 0; ci < CINL; ci++) {
        const int buf = ci & 1;
        if (ci + 1 < CINL) stage(ci + 1, buf ^ 1);   // prefetch overlaps compute
#pragma unroll
        for (int kz = 0; kz < 3; kz++)
#pragma unroll
            for (int ky = 0; ky < 3; ky++)
#pragma unroll
                for (int kx = 0; kx < 3; kx++) {
                    const float* row = &ism[buf][(kz * 10 + yr + ky) * WIN + xb + kx];
                    float4 w4 = ((const float4*)wsm[buf])[(kz * 9 + ky * 3 + kx) * 8 + cog];
#pragma unroll
                    for (int j = 0; j < 8; j++) {
                        float iv = row[j];
                        a0[j] += w4.x * iv;
                        a1[j] += w4.y * iv;
                        a2[j] += w4.z * iv;
                        a3[j] += w4.w * iv;
                    }
                }
        __syncthreads();
    }

    if (y < WOUT) {
        const float rs = rsqrtf(1.f + 1e-5f);
        float* accs[4] = {a0, a1, a2, a3};
#pragma unroll
        for (int c = 0; c < 4; c++) {
            int co = cog * 4 + c;
            float s = gam[co] * rs, bb = bet[co];
#pragma unroll
            for (int j = 0; j < 8; j++) {
                int xx = xb + j;
                if (xx >= WOUT) continue;
                float val = fmaxf(accs[c][j] * s + bb, 0.f);
                if (!SPLIT) {
                    out[(((size_t)(n * 32 + co) * WOUT + zo) * WOUT + y) * WOUT + xx] = val;
                } else {
#pragma unroll
                    for (int cz = 0; cz < 2; cz++) {
                        int dz = zo - cz * 8;
                        if (dz < 0 || dz >= 12) continue;
#pragma unroll
                        for (int cy = 0; cy < 2; cy++) {
                            int dy = y - cy * 8;
                            if (dy < 0 || dy >= 12) continue;
#pragma unroll
                            for (int cx = 0; cx < 2; cx++) {
                                int dx = xx - cx * 8;
                                if (dx < 0 || dx >= 12) continue;
                                int b = n * 8 + (cz << 2) + (cy << 1) + cx;
                                out[((size_t)(b * 32 + co) * 1728) + dz * 144 + dy * 12 + dx] = val;
                            }
                        }
                    }
                }
            }
        }
    }
}

// ---------------------------------------------------------------------------
// Launch
// ---------------------------------------------------------------------------
extern "C" void kernel_launch(void* const* d_in, const int* in_sizes, int n_in,
                              void* d_out, int out_size) {
    const float* prev  = (const float*)d_in[0];
    const float* tsdf  = (const float*)d_in[1];
    const float* w_up  = (const float*)d_in[2];
    const float* w_c0  = (const float*)d_in[3];
    const float* g_c0  = (const float*)d_in[4];
    const float* b_c0  = (const float*)d_in[5];
    const float* w_c1  = (const float*)d_in[6];
    const float* g_c1  = (const float*)d_in[7];
    const float* b_c1  = (const float*)d_in[8];
    const float* w_c2  = (const float*)d_in[9];
    const float* g_c2  = (const float*)d_in[10];
    const float* b_c2  = (const float*)d_in[11];
    const float* w_p0  = (const float*)d_in[12];
    const float* g_p0  = (const float*)d_in[13];
    const float* b_p0  = (const float*)d_in[14];
    const float* w_p1  = (const float*)d_in[15];
    const float* g_p1  = (const float*)d_in[16];
    const float* b_p1  = (const float*)d_in[17];
    const float* w_lin = (const float*)d_in[18];
    const float* b_lin = (const float*)d_in[19];
    float* out = (float*)d_out;

    float* dx0; cudaGetSymbolAddress((void**)&dx0, g_x0);
    float* dx1; cudaGetSymbolAddress((void**)&dx1, g_x1);
    float* dx2; cudaGetSymbolAddress((void**)&dx2, g_x2);

    // build x0 = concat(upsample(prev), tsdf slice)
    {
        int tot = NB * UPD * UPD * UPD;
        tsdf_slice_kernel<<<(tot + 255) / 256, 256>>>(tsdf);
    }
    upsample_kernel<<<dim3(NB, UPD), 704>>>(prev, w_up);

    // conv chain (c2 fused with split_tree scatter into d_out)
    conv3_bnrelu_kernel<33, 24, false><<<dim3(24, 3, NB), 192>>>(dx0, w_c0, g_c0, b_c0, dx1);
    conv3_bnrelu_kernel<32, 22, false><<<dim3(22, 3, NB), 192>>>(dx1, w_c1, g_c1, b_c1, dx2);
    conv3_bnrelu_kernel<32, 20, true ><<<dim3(20, 3, NB), 192>>>(dx2, w_c2, g_c2, b_c2, out);

    // prediction branch (independent — last)
    pred_p0_kernel<<<64, 512>>>(prev, w_p0, g_p0, b_p0);
    pred_p1_kernel<<<64, 256>>>(w_p1, g_p1, b_p1, w_lin, b_lin, out + PRED_OFF);
}

// round 10
// speedup vs baseline: 1.6506x; 1.0043x over previous
#include <cuda_runtime.h>
#include <math.h>

// ---------------------------------------------------------------------------
// Problem constants
// ---------------------------------------------------------------------------
#define NB    64
#define CIN   32
#define COUT  32
#define SUBD  12
#define UPD   26
#define D0    24
#define D1    22
#define D2    20
#define TSD   74
#define PRED_OFF 28311552 // 512*32*12*12*12

// ---------------------------------------------------------------------------
// Packed fp32x2 helpers (kept ONLY for upsample where measured speed-neutral)
// ---------------------------------------------------------------------------
__device__ __forceinline__ void ffma2(unsigned long long& d,
                                      unsigned long long a,
                                      unsigned long long b) {
    asm("fma.rn.f32x2 %0, %1, %2, %0;" : "+l"(d) : "l"(a), "l"(b));
}
__device__ __forceinline__ unsigned long long pk2(float lo, float hi) {
    unsigned long long r;
    asm("mov.b64 %0, {%1, %2};" : "=l"(r) : "f"(lo), "f"(hi));
    return r;
}
__device__ __forceinline__ void upk2(unsigned long long v, float& lo, float& hi) {
    asm("mov.b64 {%0, %1}, %2;" : "=f"(lo), "=f"(hi) : "l"(v));
}

// ---------------------------------------------------------------------------
// Device scratch (static allocation — no cudaMalloc allowed)
// ---------------------------------------------------------------------------
__device__ float g_x0[NB * 33 * UPD * UPD * UPD];
__device__ float g_x1[NB * 32 * D0 * D0 * D0];
__device__ float g_x2[NB * 32 * D1 * D1 * D1];
__device__ float g_h0[NB * 16 * 10 * 10 * 10];

// ---------------------------------------------------------------------------
// Prediction branch, stage 0: conv3d 32->16 (12^3 -> 10^3) + BN + ReLU
// ---------------------------------------------------------------------------
__global__ void pred_p0_kernel(const float* __restrict__ prev,
                               const float* __restrict__ w,    // [16][32][27]
                               const float* __restrict__ gam,
                               const float* __restrict__ bet) {
    const int n = blockIdx.x;
    const int tid = threadIdx.x;
    __shared__ float ch[1728];
    __shared__ float wsm[432];

    float acc[2][16];
#pragma unroll
    for (int i = 0; i < 2; i++)
#pragma unroll
        for (int c = 0; c < 16; c++) acc[i][c] = 0.f;

    const int p0 = tid, p1 = tid + 512;
    const int z0 = p0 / 100, y0 = (p0 / 10) % 10, x0 = p0 % 10;
    const int z1 = p1 / 100, y1 = (p1 / 10) % 10, x1 = p1 % 10;
    const bool v0 = (p0 < 1000), v1 = (p1 < 1000);

    for (int ci = 0; ci < 32; ci++) {
        for (int t = tid; t < 1728; t += 512)
            ch[t] = prev[(n * 32 + ci) * 1728 + t];
        if (tid < 432) {
            int co = tid / 27, tap = tid % 27;
            wsm[tid] = w[(co * 32 + ci) * 27 + tap];
        }
        __syncthreads();
#pragma unroll
        for (int kz = 0; kz < 3; kz++)
#pragma unroll
            for (int ky = 0; ky < 3; ky++)
#pragma unroll
                for (int kx = 0; kx < 3; kx++) {
                    const int tap = kz * 9 + ky * 3 + kx;
                    float iv0 = v0 ? ch[(z0 + kz) * 144 + (y0 + ky) * 12 + (x0 + kx)] : 0.f;
                    float iv1 = v1 ? ch[(z1 + kz) * 144 + (y1 + ky) * 12 + (x1 + kx)] : 0.f;
#pragma unroll
                    for (int co = 0; co < 16; co++) {
                        float wv = wsm[co * 27 + tap];
                        acc[0][co] += wv * iv0;
                        acc[1][co] += wv * iv1;
                    }
                }
        __syncthreads();
    }
    const float rs = rsqrtf(1.f + 1e-5f);
#pragma unroll
    for (int co = 0; co < 16; co++) {
        float s = gam[co] * rs, bb = bet[co];
        if (v0) g_h0[(n * 16 + co) * 1000 + p0] = fmaxf(acc[0][co] * s + bb, 0.f);
        if (v1) g_h0[(n * 16 + co) * 1000 + p1] = fmaxf(acc[1][co] * s + bb, 0.f);
    }
}

// ---------------------------------------------------------------------------
// Prediction branch, stage 1
// ---------------------------------------------------------------------------
__global__ void pred_p1_kernel(const float* __restrict__ w1,   // [8][16][27]
                               const float* __restrict__ g1,
                               const float* __restrict__ b1,
                               const float* __restrict__ wl,   // [3][8]
                               const float* __restrict__ bl,
                               float* __restrict__ out_pred) {
    const int n = blockIdx.x;
    const int tid = threadIdx.x;
    __shared__ float hp[16 * 125];
    __shared__ float c2[8 * 27];
    __shared__ float pl[8];

    for (int t = tid; t < 2000; t += 256) {
        int co = t / 125, p = t % 125;
        int z = p / 25, y = (p / 5) % 5, x = p % 5;
        const float* hb = g_h0 + (n * 16 + co) * 1000;
        float m = -INFINITY;
#pragma unroll
        for (int dz = 0; dz < 2; dz++)
#pragma unroll
            for (int dy = 0; dy < 2; dy++)
#pragma unroll
                for (int dx = 0; dx < 2; dx++)
                    m = fmaxf(m, hb[(2 * z + dz) * 100 + (2 * y + dy) * 10 + (2 * x + dx)]);
        hp[t] = m;
    }
    __syncthreads();
    if (tid < 216) {
        int co = tid / 27, p = tid % 27;
        int z = p / 9, y = (p / 3) % 3, x = p % 3;
        float acc = 0.f;
        for (int ci = 0; ci < 16; ci++)
#pragma unroll
            for (int kz = 0; kz < 3; kz++)
#pragma unroll
                for (int ky = 0; ky < 3; ky++)
#pragma unroll
                    for (int kx = 0; kx < 3; kx++)
                        acc += hp[ci * 125 + (z + kz) * 25 + (y + ky) * 5 + (x + kx)] *
                               __ldg(&w1[(co * 16 + ci) * 27 + kz * 9 + ky * 3 + kx]);
        const float rs = rsqrtf(1.f + 1e-5f);
        c2[tid] = fmaxf(acc * g1[co] * rs + b1[co], 0.f);
    }
    __syncthreads();
    if (tid < 8) {
        float m = -INFINITY;
#pragma unroll
        for (int dz = 0; dz < 2; dz++)
#pragma unroll
            for (int dy = 0; dy < 2; dy++)
#pragma unroll
                for (int dx = 0; dx < 2; dx++)
                    m = fmaxf(m, c2[tid * 27 + dz * 9 + dy * 3 + dx]);
        pl[tid] = m;
    }
    __syncthreads();
    if (tid < 3) {
        float acc = bl[tid];
#pragma unroll
        for (int j = 0; j < 8; j++) acc += pl[j] * wl[tid * 8 + j];
        out_pred[n * 3 + tid] = acc;
    }
}

// ---------------------------------------------------------------------------
// tsdf slice -> channel 32 of x0
// ---------------------------------------------------------------------------
__global__ void tsdf_slice_kernel(const float* __restrict__ tsdf) {
    int idx = blockIdx.x * blockDim.x + threadIdx.x;
    const int TOT = NB * UPD * UPD * UPD;
    if (idx >= TOT) return;
    int n = idx / (UPD * UPD * UPD);
    int p = idx % (UPD * UPD * UPD);
    int z = p / (UPD * UPD), y = (p / UPD) % UPD, x = p % UPD;
    int a = n >> 4, b = (n >> 2) & 3, c = n & 3;
    float v = tsdf[(a * 16 + z) * TSD * TSD + (b * 16 + y) * TSD + (c * 16 + x)];
    g_x0[(n * 33 + 32) * (UPD * UPD * UPD) + p] = v;
}

// ---------------------------------------------------------------------------
// ConvTranspose upsample. NEW (round 10): double-buffered weight staging —
// prefetch ci+1 weights while computing ci (was: LDG latency exposed behind
// a barrier 32x per CTA; issue was 19.8%).
// ---------------------------------------------------------------------------
__global__ void upsample_kernel(const float* __restrict__ prev,
                                const float* __restrict__ wup) { // [co][ci][4][4][4]
    const int n = blockIdx.x;
    const int z = blockIdx.y;
    const int tid = threadIdx.x;
    __shared__ float ism[2 * 32 * 144];
    __shared__ __align__(16) float wsm[2][1024];

    const int izA = z >> 1;
    const int izB = izA - 1;

    for (int t = tid; t < 2 * 32 * 144; t += blockDim.x) {
        int kzi = t / (32 * 144);
        int rem = t % (32 * 144);
        int ci = rem / 144, pi = rem % 144;
        int iz = kzi ? izB : izA;
        float v = 0.f;
        if (iz >= 0 && iz < 12) v = prev[((n * 32 + ci) * 12 + iz) * 144 + pi];
        ism[t] = v;
    }

    const int p = tid;
    const bool pv = (p < 676);
    const int y = p / 26, x = p % 26;
    const int iyA = y >> 1, ixA = x >> 1;
    const int kyb = y & 1, kxb = x & 1;

    // stage weights for channel ci into buffer buf
    auto stagew = [&](int ci, int buf) {
        for (int t = tid; t < 1024; t += blockDim.x) {
            int kk = t >> 5;
            int co = t & 31;
            int kzi = kk >> 4, ky = (kk >> 2) & 3, kx = kk & 3;
            int kz = (z & 1) + 2 * kzi;
            wsm[buf][t] = wup[((co * 32 + ci) * 4 + kz) * 16 + ky * 4 + kx];
        }
    };

    unsigned long long acc[16];
#pragma unroll
    for (int i = 0; i < 16; i++) acc[i] = 0ull;

    stagew(0, 0);
    __syncthreads();   // also covers ism staging

    for (int ci = 0; ci < 32; ci++) {
        const int buf = ci & 1;
        if (ci + 1 < 32) stagew(ci + 1, buf ^ 1);   // prefetch overlaps compute
        if (pv) {
            const float* ib = ism + ci * 144;
#pragma unroll
            for (int kzi = 0; kzi < 2; kzi++)
#pragma unroll
                for (int kyi = 0; kyi < 2; kyi++)
#pragma unroll
                    for (int kxi = 0; kxi < 2; kxi++) {
                        int iy = iyA - kyi, ix = ixA - kxi;
                        if (iy < 0 || iy >= 12 || ix < 0 || ix >= 12) continue;
                        float iv = ib[kzi * 4608 + iy * 12 + ix];
                        unsigned long long ivp = pk2(iv, iv);
                        int kk = (kzi * 4 + (kyb + 2 * kyi)) * 4 + (kxb + 2 * kxi);
                        const ulonglong2* w2p = (const ulonglong2*)wsm[buf] + kk * 8;
#pragma unroll
                        for (int q = 0; q < 8; q++) {
                            ulonglong2 ww = w2p[q];
                            ffma2(acc[2 * q + 0], ivp, ww.x);
                            ffma2(acc[2 * q + 1], ivp, ww.y);
                        }
                    }
        }
        __syncthreads();   // staging of ci+1 complete; wsm[buf] free at ci+2
    }
    if (pv) {
#pragma unroll
        for (int k = 0; k < 16; k++) {
            float lo, hi;
            upk2(acc[k], lo, hi);
            g_x0[(n * 33 + 2 * k + 0) * (UPD * UPD * UPD) + z * 676 + p] = lo;
            g_x0[(n * 33 + 2 * k + 1) * (UPD * UPD * UPD) + z * 676 + p] = hi;
        }
    }
}

// ---------------------------------------------------------------------------
// Conv3d k=3 valid + BN + ReLU. Round-9 proven version (scalar inner loop,
// double-buffered staging, hoisted staging addresses). UNCHANGED.
// ---------------------------------------------------------------------------
template <int CINL, int WOUT, bool SPLIT>
__global__ void conv3_bnrelu_kernel(const float* __restrict__ in,
                                    const float* __restrict__ w,   // [32][CINL][27]
                                    const float* __restrict__ gam,
                                    const float* __restrict__ bet,
                                    float* __restrict__ out) {
    constexpr int WIN = WOUT + 2;
    constexpr int ISM  = 3 * 10 * WIN;
    constexpr int NSTG = (ISM + 191) / 192;
    constexpr int NW   = (864 + 191) / 192;
    constexpr int CH3  = WIN * WIN * WIN;

    const int zo = blockIdx.x;
    const int y0 = blockIdx.y * 8;
    const int n = blockIdx.z;

    __shared__ float ism[2][ISM];
    __shared__ __align__(16) float wsm[2][27 * 32];

    const int tid = threadIdx.x;
    const int cog = tid & 7;
    const int sp = tid >> 3;
    const int xg = sp % 3;
    const int yr = sp / 3;
    const int xb = xg * 8;
    const int y = y0 + yr;

    int   s_off[NSTG];
    int   g_off[NSTG];
#pragma unroll
    for (int k = 0; k < NSTG; k++) {
        int t = tid + k * 192;
        if (t < ISM) {
            int iz = t / (10 * WIN);
            int rem = t - iz * 10 * WIN;
            int iy = rem / WIN;
            int ix = rem - iy * WIN;
            int gy = y0 + iy;
            s_off[k] = t;
            g_off[k] = (gy < WIN) ? ((zo + iz) * WIN * WIN + gy * WIN + ix) : -1;
        } else {
            s_off[k] = -1;
            g_off[k] = -1;
        }
    }
    int wg_off[NW];
    int ws_off[NW];
#pragma unroll
    for (int k = 0; k < NW; k++) {
        int t = tid + k * 192;
        if (t < 864) {
            int tap = t >> 5, co = t & 31;
            ws_off[k] = t;
            wg_off[k] = (co * CINL) * 27 + tap;
        } else {
            ws_off[k] = -1;
            wg_off[k] = -1;
        }
    }

    float a0[8], a1[8], a2[8], a3[8];
#pragma unroll
    for (int j = 0; j < 8; j++) { a0[j] = a1[j] = a2[j] = a3[j] = 0.f; }

    const float* inb = in + (size_t)n * CINL * CH3;

    auto stage = [&](int ci, int buf) {
        const float* inc = inb + (size_t)ci * CH3;
#pragma unroll
        for (int k = 0; k < NSTG; k++) {
            if (s_off[k] >= 0)
                ism[buf][s_off[k]] = (g_off[k] >= 0) ? inc[g_off[k]] : 0.f;
        }
        const int wci = ci * 27;
#pragma unroll
        for (int k = 0; k < NW; k++) {
            if (ws_off[k] >= 0)
                wsm[buf][ws_off[k]] = w[wg_off[k] + wci];
        }
    };

    stage(0, 0);
    __syncthreads();

    for (int ci = 0; ci < CINL; ci++) {
        const int buf = ci & 1;
        if (ci + 1 < CINL) stage(ci + 1, buf ^ 1);
#pragma unroll
        for (int kz = 0; kz < 3; kz++)
#pragma unroll
            for (int ky = 0; ky < 3; ky++)
#pragma unroll
                for (int kx = 0; kx < 3; kx++) {
                    const float* row = &ism[buf][(kz * 10 + yr + ky) * WIN + xb + kx];
                    float4 w4 = ((const float4*)wsm[buf])[(kz * 9 + ky * 3 + kx) * 8 + cog];
#pragma unroll
                    for (int j = 0; j < 8; j++) {
                        float iv = row[j];
                        a0[j] += w4.x * iv;
                        a1[j] += w4.y * iv;
                        a2[j] += w4.z * iv;
                        a3[j] += w4.w * iv;
                    }
                }
        __syncthreads();
    }

    if (y < WOUT) {
        const float rs = rsqrtf(1.f + 1e-5f);
        float* accs[4] = {a0, a1, a2, a3};
#pragma unroll
        for (int c = 0; c < 4; c++) {
            int co = cog * 4 + c;
            float s = gam[co] * rs, bb = bet[co];
#pragma unroll
            for (int j = 0; j < 8; j++) {
                int xx = xb + j;
                if (xx >= WOUT) continue;
                float val = fmaxf(accs[c][j] * s + bb, 0.f);
                if (!SPLIT) {
                    out[(((size_t)(n * 32 + co) * WOUT + zo) * WOUT + y) * WOUT + xx] = val;
                } else {
#pragma unroll
                    for (int cz = 0; cz < 2; cz++) {
                        int dz = zo - cz * 8;
                        if (dz < 0 || dz >= 12) continue;
#pragma unroll
                        for (int cy = 0; cy < 2; cy++) {
                            int dy = y - cy * 8;
                            if (dy < 0 || dy >= 12) continue;
#pragma unroll
                            for (int cx = 0; cx < 2; cx++) {
                                int dx = xx - cx * 8;
                                if (dx < 0 || dx >= 12) continue;
                                int b = n * 8 + (cz << 2) + (cy << 1) + cx;
                                out[((size_t)(b * 32 + co) * 1728) + dz * 144 + dy * 12 + dx] = val;
                            }
                        }
                    }
                }
            }
        }
    }
}

// ---------------------------------------------------------------------------
// Launch
// ---------------------------------------------------------------------------
extern "C" void kernel_launch(void* const* d_in, const int* in_sizes, int n_in,
                              void* d_out, int out_size) {
    const float* prev  = (const float*)d_in[0];
    const float* tsdf  = (const float*)d_in[1];
    const float* w_up  = (const float*)d_in[2];
    const float* w_c0  = (const float*)d_in[3];
    const float* g_c0  = (const float*)d_in[4];
    const float* b_c0  = (const float*)d_in[5];
    const float* w_c1  = (const float*)d_in[6];
    const float* g_c1  = (const float*)d_in[7];
    const float* b_c1  = (const float*)d_in[8];
    const float* w_c2  = (const float*)d_in[9];
    const float* g_c2  = (const float*)d_in[10];
    const float* b_c2  = (const float*)d_in[11];
    const float* w_p0  = (const float*)d_in[12];
    const float* g_p0  = (const float*)d_in[13];
    const float* b_p0  = (const float*)d_in[14];
    const float* w_p1  = (const float*)d_in[15];
    const float* g_p1  = (const float*)d_in[16];
    const float* b_p1  = (const float*)d_in[17];
    const float* w_lin = (const float*)d_in[18];
    const float* b_lin = (const float*)d_in[19];
    float* out = (float*)d_out;

    float* dx0; cudaGetSymbolAddress((void**)&dx0, g_x0);
    float* dx1; cudaGetSymbolAddress((void**)&dx1, g_x1);
    float* dx2; cudaGetSymbolAddress((void**)&dx2, g_x2);

    // build x0 = concat(upsample(prev), tsdf slice)
    {
        int tot = NB * UPD * UPD * UPD;
        tsdf_slice_kernel<<<(tot + 255) / 256, 256>>>(tsdf);
    }
    upsample_kernel<<<dim3(NB, UPD), 704>>>(prev, w_up);

    // conv chain (c2 fused with split_tree scatter into d_out)
    conv3_bnrelu_kernel<33, 24, false><<<dim3(24, 3, NB), 192>>>(dx0, w_c0, g_c0, b_c0, dx1);
    conv3_bnrelu_kernel<32, 22, false><<<dim3(22, 3, NB), 192>>>(dx1, w_c1, g_c1, b_c1, dx2);
    conv3_bnrelu_kernel<32, 20, true ><<<dim3(20, 3, NB), 192>>>(dx2, w_c2, g_c2, b_c2, out);

    // prediction branch (independent — last)
    pred_p0_kernel<<<64, 512>>>(prev, w_p0, g_p0, b_p0);
    pred_p1_kernel<<<64, 256>>>(w_p1, g_p1, b_p1, w_lin, b_lin, out + PRED_OFF);
}

// round 12
// speedup vs baseline: 1.9195x; 1.1629x over previous
#include <cuda_runtime.h>
#include <math.h>

// ---------------------------------------------------------------------------
// Problem constants
// ---------------------------------------------------------------------------
#define NB    64
#define CIN   32
#define COUT  32
#define SUBD  12
#define UPD   26
#define D0    24
#define D1    22
#define D2    20
#define TSD   74
#define PRED_OFF 28311552 // 512*32*12*12*12

// ---------------------------------------------------------------------------
// Packed fp32x2 helpers (upsample only)
// ---------------------------------------------------------------------------
__device__ __forceinline__ void ffma2(unsigned long long& d,
                                      unsigned long long a,
                                      unsigned long long b) {
    asm("fma.rn.f32x2 %0, %1, %2, %0;" : "+l"(d) : "l"(a), "l"(b));
}
__device__ __forceinline__ unsigned long long pk2(float lo, float hi) {
    unsigned long long r;
    asm("mov.b64 %0, {%1, %2};" : "=l"(r) : "f"(lo), "f"(hi));
    return r;
}
__device__ __forceinline__ void upk2(unsigned long long v, float& lo, float& hi) {
    asm("mov.b64 {%0, %1}, %2;" : "=f"(lo), "=f"(hi) : "l"(v));
}

// ---------------------------------------------------------------------------
// Device scratch (static allocation — no cudaMalloc allowed)
// ---------------------------------------------------------------------------
__device__ float g_x0[NB * 33 * UPD * UPD * UPD];
__device__ float g_x1[NB * 32 * D0 * D0 * D0];
__device__ float g_x2[NB * 32 * D1 * D1 * D1];
__device__ float g_h0[NB * 16 * 10 * 10 * 10];

// ---------------------------------------------------------------------------
// Prediction branch, stage 0: conv3d 32->16 (12^3 -> 10^3) + BN + ReLU
// ---------------------------------------------------------------------------
__global__ void pred_p0_kernel(const float* __restrict__ prev,
                               const float* __restrict__ w,    // [16][32][27]
                               const float* __restrict__ gam,
                               const float* __restrict__ bet) {
    const int n = blockIdx.x;
    const int tid = threadIdx.x;
    __shared__ float ch[1728];
    __shared__ float wsm[432];

    float acc[2][16];
#pragma unroll
    for (int i = 0; i < 2; i++)
#pragma unroll
        for (int c = 0; c < 16; c++) acc[i][c] = 0.f;

    const int p0 = tid, p1 = tid + 512;
    const int z0 = p0 / 100, y0 = (p0 / 10) % 10, x0 = p0 % 10;
    const int z1 = p1 / 100, y1 = (p1 / 10) % 10, x1 = p1 % 10;
    const bool v0 = (p0 < 1000), v1 = (p1 < 1000);

    for (int ci = 0; ci < 32; ci++) {
        for (int t = tid; t < 1728; t += 512)
            ch[t] = prev[(n * 32 + ci) * 1728 + t];
        if (tid < 432) {
            int co = tid / 27, tap = tid % 27;
            wsm[tid] = w[(co * 32 + ci) * 27 + tap];
        }
        __syncthreads();
#pragma unroll
        for (int kz = 0; kz < 3; kz++)
#pragma unroll
            for (int ky = 0; ky < 3; ky++)
#pragma unroll
                for (int kx = 0; kx < 3; kx++) {
                    const int tap = kz * 9 + ky * 3 + kx;
                    float iv0 = v0 ? ch[(z0 + kz) * 144 + (y0 + ky) * 12 + (x0 + kx)] : 0.f;
                    float iv1 = v1 ? ch[(z1 + kz) * 144 + (y1 + ky) * 12 + (x1 + kx)] : 0.f;
#pragma unroll
                    for (int co = 0; co < 16; co++) {
                        float wv = wsm[co * 27 + tap];
                        acc[0][co] += wv * iv0;
                        acc[1][co] += wv * iv1;
                    }
                }
        __syncthreads();
    }
    const float rs = rsqrtf(1.f + 1e-5f);
#pragma unroll
    for (int co = 0; co < 16; co++) {
        float s = gam[co] * rs, bb = bet[co];
        if (v0) g_h0[(n * 16 + co) * 1000 + p0] = fmaxf(acc[0][co] * s + bb, 0.f);
        if (v1) g_h0[(n * 16 + co) * 1000 + p1] = fmaxf(acc[1][co] * s + bb, 0.f);
    }
}

// ---------------------------------------------------------------------------
// Prediction branch, stage 1
// ---------------------------------------------------------------------------
__global__ void pred_p1_kernel(const float* __restrict__ w1,   // [8][16][27]
                               const float* __restrict__ g1,
                               const float* __restrict__ b1,
                               const float* __restrict__ wl,   // [3][8]
                               const float* __restrict__ bl,
                               float* __restrict__ out_pred) {
    const int n = blockIdx.x;
    const int tid = threadIdx.x;
    __shared__ float hp[16 * 125];
    __shared__ float c2[8 * 27];
    __shared__ float pl[8];

    for (int t = tid; t < 2000; t += 256) {
        int co = t / 125, p = t % 125;
        int z = p / 25, y = (p / 5) % 5, x = p % 5;
        const float* hb = g_h0 + (n * 16 + co) * 1000;
        float m = -INFINITY;
#pragma unroll
        for (int dz = 0; dz < 2; dz++)
#pragma unroll
            for (int dy = 0; dy < 2; dy++)
#pragma unroll
                for (int dx = 0; dx < 2; dx++)
                    m = fmaxf(m, hb[(2 * z + dz) * 100 + (2 * y + dy) * 10 + (2 * x + dx)]);
        hp[t] = m;
    }
    __syncthreads();
    if (tid < 216) {
        int co = tid / 27, p = tid % 27;
        int z = p / 9, y = (p / 3) % 3, x = p % 3;
        float acc = 0.f;
        for (int ci = 0; ci < 16; ci++)
#pragma unroll
            for (int kz = 0; kz < 3; kz++)
#pragma unroll
                for (int ky = 0; ky < 3; ky++)
#pragma unroll
                    for (int kx = 0; kx < 3; kx++)
                        acc += hp[ci * 125 + (z + kz) * 25 + (y + ky) * 5 + (x + kx)] *
                               __ldg(&w1[(co * 16 + ci) * 27 + kz * 9 + ky * 3 + kx]);
        const float rs = rsqrtf(1.f + 1e-5f);
        c2[tid] = fmaxf(acc * g1[co] * rs + b1[co], 0.f);
    }
    __syncthreads();
    if (tid < 8) {
        float m = -INFINITY;
#pragma unroll
        for (int dz = 0; dz < 2; dz++)
#pragma unroll
            for (int dy = 0; dy < 2; dy++)
#pragma unroll
                for (int dx = 0; dx < 2; dx++)
                    m = fmaxf(m, c2[tid * 27 + dz * 9 + dy * 3 + dx]);
        pl[tid] = m;
    }
    __syncthreads();
    if (tid < 3) {
        float acc = bl[tid];
#pragma unroll
        for (int j = 0; j < 8; j++) acc += pl[j] * wl[tid * 8 + j];
        out_pred[n * 3 + tid] = acc;
    }
}

// ---------------------------------------------------------------------------
// tsdf slice -> channel 32 of x0
// ---------------------------------------------------------------------------
__global__ void tsdf_slice_kernel(const float* __restrict__ tsdf) {
    int idx = blockIdx.x * blockDim.x + threadIdx.x;
    const int TOT = NB * UPD * UPD * UPD;
    if (idx >= TOT) return;
    int n = idx / (UPD * UPD * UPD);
    int p = idx % (UPD * UPD * UPD);
    int z = p / (UPD * UPD), y = (p / UPD) % UPD, x = p % UPD;
    int a = n >> 4, b = (n >> 2) & 3, c = n & 3;
    float v = tsdf[(a * 16 + z) * TSD * TSD + (b * 16 + y) * TSD + (c * 16 + x)];
    g_x0[(n * 33 + 32) * (UPD * UPD * UPD) + p] = v;
}

// ---------------------------------------------------------------------------
// ConvTranspose upsample. Round 11: CTA computes a 16-cout HALF
// (grid (NB, UPD, 2)) so acc[8] u64 -> ~40 regs -> 2 CTAs/SM (occ 34->69%).
// Double-buffered weight staging kept.
// ---------------------------------------------------------------------------
__global__ void __launch_bounds__(704, 2)
upsample_kernel(const float* __restrict__ prev,
                const float* __restrict__ wup) { // [co][ci][4][4][4]
    const int n = blockIdx.x;
    const int z = blockIdx.y;
    const int co0 = blockIdx.z * 16;           // cout half base
    const int tid = threadIdx.x;
    __shared__ float ism[2 * 32 * 144];
    __shared__ __align__(16) float wsm[2][512];   // [kk][16 co]

    const int izA = z >> 1;
    const int izB = izA - 1;

    for (int t = tid; t < 2 * 32 * 144; t += blockDim.x) {
        int kzi = t / (32 * 144);
        int rem = t % (32 * 144);
        int ci = rem / 144, pi = rem % 144;
        int iz = kzi ? izB : izA;
        float v = 0.f;
        if (iz >= 0 && iz < 12) v = prev[((n * 32 + ci) * 12 + iz) * 144 + pi];
        ism[t] = v;
    }

    const int p = tid;
    const bool pv = (p < 676);
    const int y = p / 26, x = p % 26;
    const int iyA = y >> 1, ixA = x >> 1;
    const int kyb = y & 1, kxb = x & 1;

    // stage 16-cout weights for channel ci into buffer buf
    auto stagew = [&](int ci, int buf) {
        for (int t = tid; t < 512; t += blockDim.x) {
            int kk = t >> 4;                   // (kzi*4+ky)*4+kx
            int co = co0 + (t & 15);
            int kzi = kk >> 4 & 1, ky = (kk >> 2) & 3, kx = kk & 3;
            kzi = kk >> 4;                     // kk in [0,32): top bit = kzi
            int kz = (z & 1) + 2 * kzi;
            wsm[buf][t] = wup[((co * 32 + ci) * 4 + kz) * 16 + ky * 4 + kx];
        }
    };

    unsigned long long acc[8];                 // 16 couts as 8 pairs
#pragma unroll
    for (int i = 0; i < 8; i++) acc[i] = 0ull;

    stagew(0, 0);
    __syncthreads();   // also covers ism staging

    for (int ci = 0; ci < 32; ci++) {
        const int buf = ci & 1;
        if (ci + 1 < 32) stagew(ci + 1, buf ^ 1);   // prefetch overlaps compute
        if (pv) {
            const float* ib = ism + ci * 144;
#pragma unroll
            for (int kzi = 0; kzi < 2; kzi++)
#pragma unroll
                for (int kyi = 0; kyi < 2; kyi++)
#pragma unroll
                    for (int kxi = 0; kxi < 2; kxi++) {
                        int iy = iyA - kyi, ix = ixA - kxi;
                        if (iy < 0 || iy >= 12 || ix < 0 || ix >= 12) continue;
                        float iv = ib[kzi * 4608 + iy * 12 + ix];
                        unsigned long long ivp = pk2(iv, iv);
                        int kk = (kzi * 4 + (kyb + 2 * kyi)) * 4 + (kxb + 2 * kxi);
                        const ulonglong2* w2p = (const ulonglong2*)&wsm[buf][kk * 16];
#pragma unroll
                        for (int q = 0; q < 4; q++) {
                            ulonglong2 ww = w2p[q];
                            ffma2(acc[2 * q + 0], ivp, ww.x);
                            ffma2(acc[2 * q + 1], ivp, ww.y);
                        }
                    }
        }
        __syncthreads();   // staging of ci+1 complete; wsm[buf] free at ci+2
    }
    if (pv) {
#pragma unroll
        for (int k = 0; k < 8; k++) {
            float lo, hi;
            upk2(acc[k], lo, hi);
            g_x0[(n * 33 + co0 + 2 * k + 0) * (UPD * UPD * UPD) + z * 676 + p] = lo;
            g_x0[(n * 33 + co0 + 2 * k + 1) * (UPD * UPD * UPD) + z * 676 + p] = hi;
        }
    }
}

// ---------------------------------------------------------------------------
// Conv3d k=3 valid + BN + ReLU. Round-9 proven version. UNCHANGED.
// ---------------------------------------------------------------------------
template <int CINL, int WOUT, bool SPLIT>
__global__ void conv3_bnrelu_kernel(const float* __restrict__ in,
                                    const float* __restrict__ w,   // [32][CINL][27]
                                    const float* __restrict__ gam,
                                    const float* __restrict__ bet,
                                    float* __restrict__ out) {
    constexpr int WIN = WOUT + 2;
    constexpr int ISM  = 3 * 10 * WIN;
    constexpr int NSTG = (ISM + 191) / 192;
    constexpr int NW   = (864 + 191) / 192;
    constexpr int CH3  = WIN * WIN * WIN;

    const int zo = blockIdx.x;
    const int y0 = blockIdx.y * 8;
    const int n = blockIdx.z;

    __shared__ float ism[2][ISM];
    __shared__ __align__(16) float wsm[2][27 * 32];

    const int tid = threadIdx.x;
    const int cog = tid & 7;
    const int sp = tid >> 3;
    const int xg = sp % 3;
    const int yr = sp / 3;
    const int xb = xg * 8;
    const int y = y0 + yr;

    int   s_off[NSTG];
    int   g_off[NSTG];
#pragma unroll
    for (int k = 0; k < NSTG; k++) {
        int t = tid + k * 192;
        if (t < ISM) {
            int iz = t / (10 * WIN);
            int rem = t - iz * 10 * WIN;
            int iy = rem / WIN;
            int ix = rem - iy * WIN;
            int gy = y0 + iy;
            s_off[k] = t;
            g_off[k] = (gy < WIN) ? ((zo + iz) * WIN * WIN + gy * WIN + ix) : -1;
        } else {
            s_off[k] = -1;
            g_off[k] = -1;
        }
    }
    int wg_off[NW];
    int ws_off[NW];
#pragma unroll
    for (int k = 0; k < NW; k++) {
        int t = tid + k * 192;
        if (t < 864) {
            int tap = t >> 5, co = t & 31;
            ws_off[k] = t;
            wg_off[k] = (co * CINL) * 27 + tap;
        } else {
            ws_off[k] = -1;
            wg_off[k] = -1;
        }
    }

    float a0[8], a1[8], a2[8], a3[8];
#pragma unroll
    for (int j = 0; j < 8; j++) { a0[j] = a1[j] = a2[j] = a3[j] = 0.f; }

    const float* inb = in + (size_t)n * CINL * CH3;

    auto stage = [&](int ci, int buf) {
        const float* inc = inb + (size_t)ci * CH3;
#pragma unroll
        for (int k = 0; k < NSTG; k++) {
            if (s_off[k] >= 0)
                ism[buf][s_off[k]] = (g_off[k] >= 0) ? inc[g_off[k]] : 0.f;
        }
        const int wci = ci * 27;
#pragma unroll
        for (int k = 0; k < NW; k++) {
            if (ws_off[k] >= 0)
                wsm[buf][ws_off[k]] = w[wg_off[k] + wci];
        }
    };

    stage(0, 0);
    __syncthreads();

    for (int ci = 0; ci < CINL; ci++) {
        const int buf = ci & 1;
        if (ci + 1 < CINL) stage(ci + 1, buf ^ 1);
#pragma unroll
        for (int kz = 0; kz < 3; kz++)
#pragma unroll
            for (int ky = 0; ky < 3; ky++)
#pragma unroll
                for (int kx = 0; kx < 3; kx++) {
                    const float* row = &ism[buf][(kz * 10 + yr + ky) * WIN + xb + kx];
                    float4 w4 = ((const float4*)wsm[buf])[(kz * 9 + ky * 3 + kx) * 8 + cog];
#pragma unroll
                    for (int j = 0; j < 8; j++) {
                        float iv = row[j];
                        a0[j] += w4.x * iv;
                        a1[j] += w4.y * iv;
                        a2[j] += w4.z * iv;
                        a3[j] += w4.w * iv;
                    }
                }
        __syncthreads();
    }

    if (y < WOUT) {
        const float rs = rsqrtf(1.f + 1e-5f);
        float* accs[4] = {a0, a1, a2, a3};
#pragma unroll
        for (int c = 0; c < 4; c++) {
            int co = cog * 4 + c;
            float s = gam[co] * rs, bb = bet[co];
#pragma unroll
            for (int j = 0; j < 8; j++) {
                int xx = xb + j;
                if (xx >= WOUT) continue;
                float val = fmaxf(accs[c][j] * s + bb, 0.f);
                if (!SPLIT) {
                    out[(((size_t)(n * 32 + co) * WOUT + zo) * WOUT + y) * WOUT + xx] = val;
                } else {
#pragma unroll
                    for (int cz = 0; cz < 2; cz++) {
                        int dz = zo - cz * 8;
                        if (dz < 0 || dz >= 12) continue;
#pragma unroll
                        for (int cy = 0; cy < 2; cy++) {
                            int dy = y - cy * 8;
                            if (dy < 0 || dy >= 12) continue;
#pragma unroll
                            for (int cx = 0; cx < 2; cx++) {
                                int dx = xx - cx * 8;
                                if (dx < 0 || dx >= 12) continue;
                                int b = n * 8 + (cz << 2) + (cy << 1) + cx;
                                out[((size_t)(b * 32 + co) * 1728) + dz * 144 + dy * 12 + dx] = val;
                            }
                        }
                    }
                }
            }
        }
    }
}

// ---------------------------------------------------------------------------
// Launch
// ---------------------------------------------------------------------------
extern "C" void kernel_launch(void* const* d_in, const int* in_sizes, int n_in,
                              void* d_out, int out_size) {
    const float* prev  = (const float*)d_in[0];
    const float* tsdf  = (const float*)d_in[1];
    const float* w_up  = (const float*)d_in[2];
    const float* w_c0  = (const float*)d_in[3];
    const float* g_c0  = (const float*)d_in[4];
    const float* b_c0  = (const float*)d_in[5];
    const float* w_c1  = (const float*)d_in[6];
    const float* g_c1  = (const float*)d_in[7];
    const float* b_c1  = (const float*)d_in[8];
    const float* w_c2  = (const float*)d_in[9];
    const float* g_c2  = (const float*)d_in[10];
    const float* b_c2  = (const float*)d_in[11];
    const float* w_p0  = (const float*)d_in[12];
    const float* g_p0  = (const float*)d_in[13];
    const float* b_p0  = (const float*)d_in[14];
    const float* w_p1  = (const float*)d_in[15];
    const float* g_p1  = (const float*)d_in[16];
    const float* b_p1  = (const float*)d_in[17];
    const float* w_lin = (const float*)d_in[18];
    const float* b_lin = (const float*)d_in[19];
    float* out = (float*)d_out;

    float* dx0; cudaGetSymbolAddress((void**)&dx0, g_x0);
    float* dx1; cudaGetSymbolAddress((void**)&dx1, g_x1);
    float* dx2; cudaGetSymbolAddress((void**)&dx2, g_x2);

    // build x0 = concat(upsample(prev), tsdf slice)
    {
        int tot = NB * UPD * UPD * UPD;
        tsdf_slice_kernel<<<(tot + 255) / 256, 256>>>(tsdf);
    }
    upsample_kernel<<<dim3(NB, UPD, 2), 704>>>(prev, w_up);

    // conv chain (c2 fused with split_tree scatter into d_out)
    conv3_bnrelu_kernel<33, 24, false><<<dim3(24, 3, NB), 192>>>(dx0, w_c0, g_c0, b_c0, dx1);
    conv3_bnrelu_kernel<32, 22, false><<<dim3(22, 3, NB), 192>>>(dx1, w_c1, g_c1, b_c1, dx2);
    conv3_bnrelu_kernel<32, 20, true ><<<dim3(20, 3, NB), 192>>>(dx2, w_c2, g_c2, b_c2, out);

    // prediction branch (independent — last)
    pred_p0_kernel<<<64, 512>>>(prev, w_p0, g_p0, b_p0);
    pred_p1_kernel<<<64, 256>>>(w_p1, g_p1, b_p1, w_lin, b_lin, out + PRED_OFF);
}

// round 13
// speedup vs baseline: 2.0345x; 1.0599x over previous
#include <cuda_runtime.h>
#include <math.h>

// ---------------------------------------------------------------------------
// Problem constants
// ---------------------------------------------------------------------------
#define NB    64
#define CIN   32
#define COUT  32
#define SUBD  12
#define UPD   26
#define D0    24
#define D1    22
#define D2    20
#define TSD   74
#define PRED_OFF 28311552 // 512*32*12*12*12

// ---------------------------------------------------------------------------
// Packed fp32x2 helpers (upsample only)
// ---------------------------------------------------------------------------
__device__ __forceinline__ void ffma2(unsigned long long& d,
                                      unsigned long long a,
                                      unsigned long long b) {
    asm("fma.rn.f32x2 %0, %1, %2, %0;" : "+l"(d) : "l"(a), "l"(b));
}
__device__ __forceinline__ unsigned long long pk2(float lo, float hi) {
    unsigned long long r;
    asm("mov.b64 %0, {%1, %2};" : "=l"(r) : "f"(lo), "f"(hi));
    return r;
}
__device__ __forceinline__ void upk2(unsigned long long v, float& lo, float& hi) {
    asm("mov.b64 {%0, %1}, %2;" : "=f"(lo), "=f"(hi) : "l"(v));
}

// ---------------------------------------------------------------------------
// Device scratch (static allocation — no cudaMalloc allowed)
// ---------------------------------------------------------------------------
__device__ float g_x0[NB * 33 * UPD * UPD * UPD];
__device__ float g_x1[NB * 32 * D0 * D0 * D0];
__device__ float g_x2[NB * 32 * D1 * D1 * D1];
__device__ float g_h0[NB * 16 * 10 * 10 * 10];

// ---------------------------------------------------------------------------
// Prediction branch, stage 0: conv3d 32->16 (12^3 -> 10^3) + BN + ReLU
// ---------------------------------------------------------------------------
__global__ void pred_p0_kernel(const float* __restrict__ prev,
                               const float* __restrict__ w,    // [16][32][27]
                               const float* __restrict__ gam,
                               const float* __restrict__ bet) {
    const int n = blockIdx.x;
    const int tid = threadIdx.x;
    __shared__ float ch[1728];
    __shared__ float wsm[432];

    float acc[2][16];
#pragma unroll
    for (int i = 0; i < 2; i++)
#pragma unroll
        for (int c = 0; c < 16; c++) acc[i][c] = 0.f;

    const int p0 = tid, p1 = tid + 512;
    const int z0 = p0 / 100, y0 = (p0 / 10) % 10, x0 = p0 % 10;
    const int z1 = p1 / 100, y1 = (p1 / 10) % 10, x1 = p1 % 10;
    const bool v0 = (p0 < 1000), v1 = (p1 < 1000);

    for (int ci = 0; ci < 32; ci++) {
        for (int t = tid; t < 1728; t += 512)
            ch[t] = prev[(n * 32 + ci) * 1728 + t];
        if (tid < 432) {
            int co = tid / 27, tap = tid % 27;
            wsm[tid] = w[(co * 32 + ci) * 27 + tap];
        }
        __syncthreads();
#pragma unroll
        for (int kz = 0; kz < 3; kz++)
#pragma unroll
            for (int ky = 0; ky < 3; ky++)
#pragma unroll
                for (int kx = 0; kx < 3; kx++) {
                    const int tap = kz * 9 + ky * 3 + kx;
                    float iv0 = v0 ? ch[(z0 + kz) * 144 + (y0 + ky) * 12 + (x0 + kx)] : 0.f;
                    float iv1 = v1 ? ch[(z1 + kz) * 144 + (y1 + ky) * 12 + (x1 + kx)] : 0.f;
#pragma unroll
                    for (int co = 0; co < 16; co++) {
                        float wv = wsm[co * 27 + tap];
                        acc[0][co] += wv * iv0;
                        acc[1][co] += wv * iv1;
                    }
                }
        __syncthreads();
    }
    const float rs = rsqrtf(1.f + 1e-5f);
#pragma unroll
    for (int co = 0; co < 16; co++) {
        float s = gam[co] * rs, bb = bet[co];
        if (v0) g_h0[(n * 16 + co) * 1000 + p0] = fmaxf(acc[0][co] * s + bb, 0.f);
        if (v1) g_h0[(n * 16 + co) * 1000 + p1] = fmaxf(acc[1][co] * s + bb, 0.f);
    }
}

// ---------------------------------------------------------------------------
// Prediction branch, stage 1
// ---------------------------------------------------------------------------
__global__ void pred_p1_kernel(const float* __restrict__ w1,   // [8][16][27]
                               const float* __restrict__ g1,
                               const float* __restrict__ b1,
                               const float* __restrict__ wl,   // [3][8]
                               const float* __restrict__ bl,
                               float* __restrict__ out_pred) {
    const int n = blockIdx.x;
    const int tid = threadIdx.x;
    __shared__ float hp[16 * 125];
    __shared__ float c2[8 * 27];
    __shared__ float pl[8];

    for (int t = tid; t < 2000; t += 256) {
        int co = t / 125, p = t % 125;
        int z = p / 25, y = (p / 5) % 5, x = p % 5;
        const float* hb = g_h0 + (n * 16 + co) * 1000;
        float m = -INFINITY;
#pragma unroll
        for (int dz = 0; dz < 2; dz++)
#pragma unroll
            for (int dy = 0; dy < 2; dy++)
#pragma unroll
                for (int dx = 0; dx < 2; dx++)
                    m = fmaxf(m, hb[(2 * z + dz) * 100 + (2 * y + dy) * 10 + (2 * x + dx)]);
        hp[t] = m;
    }
    __syncthreads();
    if (tid < 216) {
        int co = tid / 27, p = tid % 27;
        int z = p / 9, y = (p / 3) % 3, x = p % 3;
        float acc = 0.f;
        for (int ci = 0; ci < 16; ci++)
#pragma unroll
            for (int kz = 0; kz < 3; kz++)
#pragma unroll
                for (int ky = 0; ky < 3; ky++)
#pragma unroll
                    for (int kx = 0; kx < 3; kx++)
                        acc += hp[ci * 125 + (z + kz) * 25 + (y + ky) * 5 + (x + kx)] *
                               __ldg(&w1[(co * 16 + ci) * 27 + kz * 9 + ky * 3 + kx]);
        const float rs = rsqrtf(1.f + 1e-5f);
        c2[tid] = fmaxf(acc * g1[co] * rs + b1[co], 0.f);
    }
    __syncthreads();
    if (tid < 8) {
        float m = -INFINITY;
#pragma unroll
        for (int dz = 0; dz < 2; dz++)
#pragma unroll
            for (int dy = 0; dy < 2; dy++)
#pragma unroll
                for (int dx = 0; dx < 2; dx++)
                    m = fmaxf(m, c2[tid * 27 + dz * 9 + dy * 3 + dx]);
        pl[tid] = m;
    }
    __syncthreads();
    if (tid < 3) {
        float acc = bl[tid];
#pragma unroll
        for (int j = 0; j < 8; j++) acc += pl[j] * wl[tid * 8 + j];
        out_pred[n * 3 + tid] = acc;
    }
}

// ---------------------------------------------------------------------------
// tsdf slice -> channel 32 of x0
// ---------------------------------------------------------------------------
__global__ void tsdf_slice_kernel(const float* __restrict__ tsdf) {
    int idx = blockIdx.x * blockDim.x + threadIdx.x;
    const int TOT = NB * UPD * UPD * UPD;
    if (idx >= TOT) return;
    int n = idx / (UPD * UPD * UPD);
    int p = idx % (UPD * UPD * UPD);
    int z = p / (UPD * UPD), y = (p / UPD) % UPD, x = p % UPD;
    int a = n >> 4, b = (n >> 2) & 3, c = n & 3;
    float v = tsdf[(a * 16 + z) * TSD * TSD + (b * 16 + y) * TSD + (c * 16 + x)];
    g_x0[(n * 33 + 32) * (UPD * UPD * UPD) + p] = v;
}

// ---------------------------------------------------------------------------
// ConvTranspose upsample. Round-12 proven version (16-cout halves, 2 CTAs/SM,
// double-buffered weights). UNCHANGED.
// ---------------------------------------------------------------------------
__global__ void __launch_bounds__(704, 2)
upsample_kernel(const float* __restrict__ prev,
                const float* __restrict__ wup) { // [co][ci][4][4][4]
    const int n = blockIdx.x;
    const int z = blockIdx.y;
    const int co0 = blockIdx.z * 16;
    const int tid = threadIdx.x;
    __shared__ float ism[2 * 32 * 144];
    __shared__ __align__(16) float wsm[2][512];

    const int izA = z >> 1;
    const int izB = izA - 1;

    for (int t = tid; t < 2 * 32 * 144; t += blockDim.x) {
        int kzi = t / (32 * 144);
        int rem = t % (32 * 144);
        int ci = rem / 144, pi = rem % 144;
        int iz = kzi ? izB : izA;
        float v = 0.f;
        if (iz >= 0 && iz < 12) v = prev[((n * 32 + ci) * 12 + iz) * 144 + pi];
        ism[t] = v;
    }

    const int p = tid;
    const bool pv = (p < 676);
    const int y = p / 26, x = p % 26;
    const int iyA = y >> 1, ixA = x >> 1;
    const int kyb = y & 1, kxb = x & 1;

    auto stagew = [&](int ci, int buf) {
        for (int t = tid; t < 512; t += blockDim.x) {
            int kk = t >> 4;
            int co = co0 + (t & 15);
            int kzi = kk >> 4;
            int ky = (kk >> 2) & 3, kx = kk & 3;
            int kz = (z & 1) + 2 * kzi;
            wsm[buf][t] = wup[((co * 32 + ci) * 4 + kz) * 16 + ky * 4 + kx];
        }
    };

    unsigned long long acc[8];
#pragma unroll
    for (int i = 0; i < 8; i++) acc[i] = 0ull;

    stagew(0, 0);
    __syncthreads();

    for (int ci = 0; ci < 32; ci++) {
        const int buf = ci & 1;
        if (ci + 1 < 32) stagew(ci + 1, buf ^ 1);
        if (pv) {
            const float* ib = ism + ci * 144;
#pragma unroll
            for (int kzi = 0; kzi < 2; kzi++)
#pragma unroll
                for (int kyi = 0; kyi < 2; kyi++)
#pragma unroll
                    for (int kxi = 0; kxi < 2; kxi++) {
                        int iy = iyA - kyi, ix = ixA - kxi;
                        if (iy < 0 || iy >= 12 || ix < 0 || ix >= 12) continue;
                        float iv = ib[kzi * 4608 + iy * 12 + ix];
                        unsigned long long ivp = pk2(iv, iv);
                        int kk = (kzi * 4 + (kyb + 2 * kyi)) * 4 + (kxb + 2 * kxi);
                        const ulonglong2* w2p = (const ulonglong2*)&wsm[buf][kk * 16];
#pragma unroll
                        for (int q = 0; q < 4; q++) {
                            ulonglong2 ww = w2p[q];
                            ffma2(acc[2 * q + 0], ivp, ww.x);
                            ffma2(acc[2 * q + 1], ivp, ww.y);
                        }
                    }
        }
        __syncthreads();
    }
    if (pv) {
#pragma unroll
        for (int k = 0; k < 8; k++) {
            float lo, hi;
            upk2(acc[k], lo, hi);
            g_x0[(n * 33 + co0 + 2 * k + 0) * (UPD * UPD * UPD) + z * 676 + p] = lo;
            g_x0[(n * 33 + co0 + 2 * k + 1) * (UPD * UPD * UPD) + z * 676 + p] = hi;
        }
    }
}

// ---------------------------------------------------------------------------
// Conv3d k=3 valid + BN + ReLU. Round-9 inner loop; round 13: occupancy
// 4 -> 5 CTAs/SM via __launch_bounds__(192, 5). Only the EXPENSIVE input
// div/mod offsets stay hoisted; cheap weight/smem offsets recomputed inline.
// SPLIT: write c2 result directly into subtree children of d_out.
// ---------------------------------------------------------------------------
template <int CINL, int WOUT, bool SPLIT>
__global__ void __launch_bounds__(192, 5)
conv3_bnrelu_kernel(const float* __restrict__ in,
                    const float* __restrict__ w,   // [32][CINL][27]
                    const float* __restrict__ gam,
                    const float* __restrict__ bet,
                    float* __restrict__ out) {
    constexpr int WIN = WOUT + 2;
    constexpr int ISM  = 3 * 10 * WIN;
    constexpr int NSTG = (ISM + 191) / 192;
    constexpr int CH3  = WIN * WIN * WIN;

    const int zo = blockIdx.x;
    const int y0 = blockIdx.y * 8;
    const int n = blockIdx.z;

    __shared__ float ism[2][ISM];
    __shared__ __align__(16) float wsm[2][27 * 32];

    const int tid = threadIdx.x;
    const int cog = tid & 7;
    const int sp = tid >> 3;
    const int xg = sp % 3;
    const int yr = sp / 3;
    const int xb = xg * 8;
    const int y = y0 + yr;

    // hoist ONLY the expensive input div/mod offsets (smem offset is tid+k*192)
    int g_off[NSTG];
#pragma unroll
    for (int k = 0; k < NSTG; k++) {
        int t = tid + k * 192;
        if (t < ISM) {
            int iz = t / (10 * WIN);
            int rem = t - iz * 10 * WIN;
            int iy = rem / WIN;
            int ix = rem - iy * WIN;
            int gy = y0 + iy;
            g_off[k] = (gy < WIN) ? ((zo + iz) * WIN * WIN + gy * WIN + ix) : -1;
        } else {
            g_off[k] = -2;   // out of range: skip store entirely
        }
    }

    float a0[8], a1[8], a2[8], a3[8];
#pragma unroll
    for (int j = 0; j < 8; j++) { a0[j] = a1[j] = a2[j] = a3[j] = 0.f; }

    const float* inb = in + (size_t)n * CINL * CH3;

    auto stage = [&](int ci, int buf) {
        const float* inc = inb + (size_t)ci * CH3;
#pragma unroll
        for (int k = 0; k < NSTG; k++) {
            if (g_off[k] != -2)
                ism[buf][tid + k * 192] = (g_off[k] >= 0) ? inc[g_off[k]] : 0.f;
        }
        // weight offsets are cheap (shift/and) — recompute inline
        const int wci = ci * 27;
        for (int t = tid; t < 864; t += 192) {
            int tap = t >> 5, co = t & 31;
            wsm[buf][t] = w[(co * CINL) * 27 + tap + wci];
        }
    };

    stage(0, 0);
    __syncthreads();

    for (int ci = 0; ci < CINL; ci++) {
        const int buf = ci & 1;
        if (ci + 1 < CINL) stage(ci + 1, buf ^ 1);
#pragma unroll
        for (int kz = 0; kz < 3; kz++)
#pragma unroll
            for (int ky = 0; ky < 3; ky++)
#pragma unroll
                for (int kx = 0; kx < 3; kx++) {
                    const float* row = &ism[buf][(kz * 10 + yr + ky) * WIN + xb + kx];
                    float4 w4 = ((const float4*)wsm[buf])[(kz * 9 + ky * 3 + kx) * 8 + cog];
#pragma unroll
                    for (int j = 0; j < 8; j++) {
                        float iv = row[j];
                        a0[j] += w4.x * iv;
                        a1[j] += w4.y * iv;
                        a2[j] += w4.z * iv;
                        a3[j] += w4.w * iv;
                    }
                }
        __syncthreads();
    }

    if (y < WOUT) {
        const float rs = rsqrtf(1.f + 1e-5f);
        float* accs[4] = {a0, a1, a2, a3};
#pragma unroll
        for (int c = 0; c < 4; c++) {
            int co = cog * 4 + c;
            float s = gam[co] * rs, bb = bet[co];
#pragma unroll
            for (int j = 0; j < 8; j++) {
                int xx = xb + j;
                if (xx >= WOUT) continue;
                float val = fmaxf(accs[c][j] * s + bb, 0.f);
                if (!SPLIT) {
                    out[(((size_t)(n * 32 + co) * WOUT + zo) * WOUT + y) * WOUT + xx] = val;
                } else {
#pragma unroll
                    for (int cz = 0; cz < 2; cz++) {
                        int dz = zo - cz * 8;
                        if (dz < 0 || dz >= 12) continue;
#pragma unroll
                        for (int cy = 0; cy < 2; cy++) {
                            int dy = y - cy * 8;
                            if (dy < 0 || dy >= 12) continue;
#pragma unroll
                            for (int cx = 0; cx < 2; cx++) {
                                int dx = xx - cx * 8;
                                if (dx < 0 || dx >= 12) continue;
                                int b = n * 8 + (cz << 2) + (cy << 1) + cx;
                                out[((size_t)(b * 32 + co) * 1728) + dz * 144 + dy * 12 + dx] = val;
                            }
                        }
                    }
                }
            }
        }
    }
}

// ---------------------------------------------------------------------------
// Launch
// ---------------------------------------------------------------------------
extern "C" void kernel_launch(void* const* d_in, const int* in_sizes, int n_in,
                              void* d_out, int out_size) {
    const float* prev  = (const float*)d_in[0];
    const float* tsdf  = (const float*)d_in[1];
    const float* w_up  = (const float*)d_in[2];
    const float* w_c0  = (const float*)d_in[3];
    const float* g_c0  = (const float*)d_in[4];
    const float* b_c0  = (const float*)d_in[5];
    const float* w_c1  = (const float*)d_in[6];
    const float* g_c1  = (const float*)d_in[7];
    const float* b_c1  = (const float*)d_in[8];
    const float* w_c2  = (const float*)d_in[9];
    const float* g_c2  = (const float*)d_in[10];
    const float* b_c2  = (const float*)d_in[11];
    const float* w_p0  = (const float*)d_in[12];
    const float* g_p0  = (const float*)d_in[13];
    const float* b_p0  = (const float*)d_in[14];
    const float* w_p1  = (const float*)d_in[15];
    const float* g_p1  = (const float*)d_in[16];
    const float* b_p1  = (const float*)d_in[17];
    const float* w_lin = (const float*)d_in[18];
    const float* b_lin = (const float*)d_in[19];
    float* out = (float*)d_out;

    float* dx0; cudaGetSymbolAddress((void**)&dx0, g_x0);
    float* dx1; cudaGetSymbolAddress((void**)&dx1, g_x1);
    float* dx2; cudaGetSymbolAddress((void**)&dx2, g_x2);

    // build x0 = concat(upsample(prev), tsdf slice)
    {
        int tot = NB * UPD * UPD * UPD;
        tsdf_slice_kernel<<<(tot + 255) / 256, 256>>>(tsdf);
    }
    upsample_kernel<<<dim3(NB, UPD, 2), 704>>>(prev, w_up);

    // conv chain (c2 fused with split_tree scatter into d_out)
    conv3_bnrelu_kernel<33, 24, false><<<dim3(24, 3, NB), 192>>>(dx0, w_c0, g_c0, b_c0, dx1);
    conv3_bnrelu_kernel<32, 22, false><<<dim3(22, 3, NB), 192>>>(dx1, w_c1, g_c1, b_c1, dx2);
    conv3_bnrelu_kernel<32, 20, true ><<<dim3(20, 3, NB), 192>>>(dx2, w_c2, g_c2, b_c2, out);

    // prediction branch (independent — last)
    pred_p0_kernel<<<64, 512>>>(prev, w_p0, g_p0, b_p0);
    pred_p1_kernel<<<64, 256>>>(w_p1, g_p1, b_p1, w_lin, b_lin, out + PRED_OFF);
}